// round 1
// baseline (speedup 1.0000x reference)
#include <cuda_runtime.h>

#define B_ 4
#define S_ 2048
#define D_ 1024
#define H_ 16
#define E_ 64
#define M_ (B_*S_)

// Scratch (device globals: no allocation allowed in kernel_launch)
__device__ __align__(16) float g_Q[B_*H_*S_*E_];   // [b][h][s][e]
__device__ __align__(16) float g_K[B_*H_*S_*E_];
__device__ __align__(16) float g_V[B_*H_*S_*E_];
__device__ __align__(16) float g_Cc[M_*H_*E_];     // concat [b][s][h*64+e] = [8192,1024]

// ---------------------------------------------------------------------------
// GEMM: C[M,N] = A[M,K] * B[K,N] + bias[N]
//   MODE 0: B(k,n) = W[h][k][e] (h=n>>6, e=n&63), out -> [b][h][s][e] (g_Q/K/V)
//   MODE 1: B(k,n) = W[k*1024+n], out -> row-major [M,1024]
// BM=128, BN=64, BK=16, 256 threads, 8x4 per thread
// ---------------------------------------------------------------------------
template<int MODE>
__global__ __launch_bounds__(256)
void gemm_kernel(const float* __restrict__ A,
                 const float* __restrict__ W,
                 const float* __restrict__ bias,
                 float* __restrict__ C)
{
    __shared__ float As_t[16][132];   // [k][m], padded
    __shared__ float Bs[16][68];      // [k][n], padded

    const int tid = threadIdx.x;
    const int tn  = tid & 15;         // n-dir 0..15 (x4)
    const int tm  = tid >> 4;         // m-dir 0..15 (x8)
    const int m0  = blockIdx.y * 128;
    const int n0  = blockIdx.x * 64;

    float acc[8][4];
    #pragma unroll
    for (int i = 0; i < 8; i++)
        #pragma unroll
        for (int j = 0; j < 4; j++) acc[i][j] = 0.f;

    for (int k0 = 0; k0 < 1024; k0 += 16) {
        // Load A tile 128x16, store transposed
        #pragma unroll
        for (int r = 0; r < 2; r++) {
            int idx = tid + r * 256;
            int row = idx >> 2;
            int k4  = idx & 3;
            float4 v = *(const float4*)&A[(m0 + row) * D_ + k0 + k4 * 4];
            As_t[k4*4+0][row] = v.x;
            As_t[k4*4+1][row] = v.y;
            As_t[k4*4+2][row] = v.z;
            As_t[k4*4+3][row] = v.w;
        }
        // Load B tile 16x64
        {
            int kr = tid >> 4;
            int n4 = tid & 15;
            const float* src;
            if (MODE == 0) {
                int h = n0 >> 6;
                src = &W[((h * D_) + (k0 + kr)) * E_ + n4 * 4];
            } else {
                src = &W[(k0 + kr) * 1024 + n0 + n4 * 4];
            }
            *(float4*)&Bs[kr][n4 * 4] = *(const float4*)src;
        }
        __syncthreads();
        #pragma unroll
        for (int k = 0; k < 16; k++) {
            float4 a0 = *(float4*)&As_t[k][tm * 8];
            float4 a1 = *(float4*)&As_t[k][tm * 8 + 4];
            float4 b  = *(float4*)&Bs[k][tn * 4];
            float av[8] = {a0.x, a0.y, a0.z, a0.w, a1.x, a1.y, a1.z, a1.w};
            float bv[4] = {b.x, b.y, b.z, b.w};
            #pragma unroll
            for (int i = 0; i < 8; i++)
                #pragma unroll
                for (int j = 0; j < 4; j++)
                    acc[i][j] += av[i] * bv[j];
        }
        __syncthreads();
    }

    float4 b4 = *(const float4*)&bias[n0 + tn * 4];
    #pragma unroll
    for (int i = 0; i < 8; i++) {
        int m = m0 + tm * 8 + i;
        float4 r;
        r.x = acc[i][0] + b4.x;
        r.y = acc[i][1] + b4.y;
        r.z = acc[i][2] + b4.z;
        r.w = acc[i][3] + b4.w;
        if (MODE == 0) {
            int b = m >> 11;          // /S_
            int s = m & 2047;
            int h = n0 >> 6;
            *(float4*)&C[((b * H_ + h) * S_ + s) * E_ + tn * 4] = r;
        } else {
            *(float4*)&C[m * 1024 + n0 + tn * 4] = r;
        }
    }
}

// ---------------------------------------------------------------------------
// Flash attention: per (b,h), 64 query rows per block, stream K/V in 64-tiles.
// 256 threads, each owns 4x4 of the 64x64 score tile and 4x4 of O.
// Dynamic smem: Qs_t[64][68] + Ks_t[64][68] + Vs[64][68] + Ps[64][68]
// ---------------------------------------------------------------------------
#define ATT_SMEM (4 * 64 * 68 * 4)

__global__ __launch_bounds__(256)
void attn_kernel(const float* __restrict__ Qg_,
                 const float* __restrict__ Kg_,
                 const float* __restrict__ Vg_,
                 float* __restrict__ Cc)
{
    extern __shared__ float sm[];
    float* Qs = sm;                 // [e][q] stride 68
    float* Ks = sm + 64 * 68;       // [e][j] stride 68
    float* Vs = sm + 2 * 64 * 68;   // [j][e] stride 68
    float* Ps = sm + 3 * 64 * 68;   // [q][j] stride 68

    const int tid = threadIdx.x;
    const int tn  = tid & 15;       // col group (x4)
    const int tm  = tid >> 4;       // row group (x4)
    const int bh  = blockIdx.y;     // b*H + h
    const int q0  = blockIdx.x * 64;

    const float* Qg = Qg_ + (size_t)bh * S_ * E_;
    const float* Kg = Kg_ + (size_t)bh * S_ * E_;
    const float* Vg = Vg_ + (size_t)bh * S_ * E_;

    // Load Q tile transposed: Qs[e][q]
    {
        int e = tid & 63;
        int r0 = tid >> 6;
        #pragma unroll
        for (int p = 0; p < 16; p++) {
            int q = r0 + p * 4;
            Qs[e * 68 + q] = Qg[(q0 + q) * E_ + e];
        }
    }

    float m_i[4], l_i[4], o[4][4];
    #pragma unroll
    for (int i = 0; i < 4; i++) {
        m_i[i] = -1e30f;
        l_i[i] = 0.f;
        #pragma unroll
        for (int j = 0; j < 4; j++) o[i][j] = 0.f;
    }

    for (int t = 0; t < S_ / 64; t++) {
        __syncthreads();   // prev PV done (and Q load visible on t=0)
        {
            int e = tid & 63;
            int r0 = tid >> 6;
            #pragma unroll
            for (int p = 0; p < 16; p++) {
                int r = r0 + p * 4;
                float kv = Kg[(t * 64 + r) * E_ + e];
                float vv = Vg[(t * 64 + r) * E_ + e];
                Ks[e * 68 + r] = kv;
                Vs[r * 68 + e] = vv;
            }
        }
        __syncthreads();

        // S = Q K^T * 0.125
        float s[4][4];
        #pragma unroll
        for (int i = 0; i < 4; i++)
            #pragma unroll
            for (int j = 0; j < 4; j++) s[i][j] = 0.f;

        #pragma unroll 8
        for (int e = 0; e < 64; e++) {
            float4 qv = *(float4*)&Qs[e * 68 + tm * 4];
            float4 kv = *(float4*)&Ks[e * 68 + tn * 4];
            float qa[4] = {qv.x, qv.y, qv.z, qv.w};
            float ka[4] = {kv.x, kv.y, kv.z, kv.w};
            #pragma unroll
            for (int i = 0; i < 4; i++)
                #pragma unroll
                for (int j = 0; j < 4; j++)
                    s[i][j] += qa[i] * ka[j];
        }

        // online softmax (row stats across the 16 tn lanes)
        #pragma unroll
        for (int i = 0; i < 4; i++) {
            #pragma unroll
            for (int j = 0; j < 4; j++) s[i][j] *= 0.125f;
            float rmax = fmaxf(fmaxf(s[i][0], s[i][1]), fmaxf(s[i][2], s[i][3]));
            #pragma unroll
            for (int off = 8; off > 0; off >>= 1)
                rmax = fmaxf(rmax, __shfl_xor_sync(0xffffffffu, rmax, off));
            float mnew = fmaxf(m_i[i], rmax);
            float corr = __expf(m_i[i] - mnew);
            float rs = 0.f;
            #pragma unroll
            for (int j = 0; j < 4; j++) {
                float p = __expf(s[i][j] - mnew);
                s[i][j] = p;
                rs += p;
            }
            #pragma unroll
            for (int off = 8; off > 0; off >>= 1)
                rs += __shfl_xor_sync(0xffffffffu, rs, off);
            l_i[i] = l_i[i] * corr + rs;
            m_i[i] = mnew;
            #pragma unroll
            for (int j = 0; j < 4; j++) o[i][j] *= corr;
            *(float4*)&Ps[(tm * 4 + i) * 68 + tn * 4] =
                make_float4(s[i][0], s[i][1], s[i][2], s[i][3]);
        }
        __syncthreads();

        // O += P * V
        #pragma unroll 8
        for (int j = 0; j < 64; j++) {
            float4 v = *(float4*)&Vs[j * 68 + tn * 4];
            #pragma unroll
            for (int i = 0; i < 4; i++) {
                float p = Ps[(tm * 4 + i) * 68 + j];
                o[i][0] += p * v.x;
                o[i][1] += p * v.y;
                o[i][2] += p * v.z;
                o[i][3] += p * v.w;
            }
        }
    }

    // epilogue: normalize and store to concat layout [b][s][h*64+e]
    const int b = bh >> 4;
    const int h = bh & 15;
    #pragma unroll
    for (int i = 0; i < 4; i++) {
        int q = q0 + tm * 4 + i;
        float inv = 1.f / l_i[i];
        float4 r = make_float4(o[i][0] * inv, o[i][1] * inv,
                               o[i][2] * inv, o[i][3] * inv);
        *(float4*)&Cc[((size_t)(b * S_ + q) * H_ + h) * E_ + tn * 4] = r;
    }
}

// ---------------------------------------------------------------------------
extern "C" void kernel_launch(void* const* d_in, const int* in_sizes, int n_in,
                              void* d_out, int out_size)
{
    const float* q  = (const float*)d_in[0];
    const float* k  = (const float*)d_in[1];
    const float* v  = (const float*)d_in[2];
    const float* Wq = (const float*)d_in[3];
    const float* bq = (const float*)d_in[4];
    const float* Wk = (const float*)d_in[5];
    const float* bk = (const float*)d_in[6];
    const float* Wv = (const float*)d_in[7];
    const float* bv = (const float*)d_in[8];
    const float* Wo = (const float*)d_in[9];
    const float* bo = (const float*)d_in[10];
    float* out = (float*)d_out;

    float *gq, *gk, *gv, *gc;
    cudaGetSymbolAddress((void**)&gq, g_Q);
    cudaGetSymbolAddress((void**)&gk, g_K);
    cudaGetSymbolAddress((void**)&gv, g_V);
    cudaGetSymbolAddress((void**)&gc, g_Cc);

    dim3 pg(16, 64);   // N/64, M/128

    gemm_kernel<0><<<pg, 256>>>(q, Wq, bq, gq);
    gemm_kernel<0><<<pg, 256>>>(k, Wk, bk, gk);
    gemm_kernel<0><<<pg, 256>>>(v, Wv, bv, gv);

    cudaFuncSetAttribute(attn_kernel,
                         cudaFuncAttributeMaxDynamicSharedMemorySize, ATT_SMEM);
    attn_kernel<<<dim3(S_ / 64, B_ * H_), 256, ATT_SMEM>>>(gq, gk, gv, gc);

    gemm_kernel<1><<<pg, 256>>>(gc, Wo, bo, out);
}

// round 2
// speedup vs baseline: 2.6692x; 2.6692x over previous
#include <cuda_runtime.h>
#include <cstdint>

#define B_ 4
#define S_ 2048
#define D_ 1024
#define H_ 16
#define E_ 64
#define M_ (B_*S_)

// Scratch (device globals: no allocation allowed in kernel_launch)
__device__ __align__(16) float g_Q[B_*H_*S_*E_];   // [b][h][s][e]
__device__ __align__(16) float g_K[B_*H_*S_*E_];
__device__ __align__(16) float g_V[B_*H_*S_*E_];
__device__ __align__(16) float g_Cc[M_*H_*E_];     // concat [b][s][h*64+e]

__device__ __forceinline__ uint32_t f2t(float x) {
    uint32_t r;
    asm("cvt.rna.tf32.f32 %0, %1;" : "=r"(r) : "f"(x));
    return r;
}

// D += A(16x8,row) * B(8x8,col) ; tf32 in, fp32 accum
__device__ __forceinline__ void mma8(float* c, const uint32_t* a, const uint32_t* b) {
    asm volatile(
        "mma.sync.aligned.m16n8k8.row.col.f32.tf32.tf32.f32 "
        "{%0,%1,%2,%3}, {%4,%5,%6,%7}, {%8,%9}, {%0,%1,%2,%3};"
        : "+f"(c[0]), "+f"(c[1]), "+f"(c[2]), "+f"(c[3])
        : "r"(a[0]), "r"(a[1]), "r"(a[2]), "r"(a[3]), "r"(b[0]), "r"(b[1]));
}

// ---------------------------------------------------------------------------
// GEMM: C[M,N] = A[M,K]*B[K,N] + bias[N], tf32 tensor cores
//   BM=128 BN=64 BK=32, 256 threads = 8 warps (4 m x 2 n), warp tile 32x32
//   MODE 0: B(k,n)=W[h][k][e] (h=n0>>6), out -> [b][h][s][e]
//   MODE 1: B(k,n)=W[k*1024+n], out row-major [M,1024]
// ---------------------------------------------------------------------------
template<int MODE>
__global__ __launch_bounds__(256)
void gemm_tc(const float* __restrict__ A, const float* __restrict__ W,
             const float* __restrict__ bias, float* __restrict__ C)
{
    __shared__ uint32_t As[128 * 36];   // [m][k], stride 36 (36%32==4 -> frag LDS conflict-free)
    __shared__ uint32_t Bs[32 * 72];    // [k][n], stride 72 (8k+n unique mod 32)

    const int tid  = threadIdx.x;
    const int lane = tid & 31;
    const int wid  = tid >> 5;
    const int wm   = wid & 3;           // 0..3 -> 32-row slices
    const int wn   = wid >> 2;          // 0..1 -> 32-col slices
    const int m0   = blockIdx.y * 128;
    const int n0   = blockIdx.x * 64;
    const int g    = lane >> 2;         // group id (row/col within frag)
    const int t    = lane & 3;          // thread-in-group

    float acc[2][4][4];
    #pragma unroll
    for (int mt = 0; mt < 2; mt++)
        #pragma unroll
        for (int nt = 0; nt < 4; nt++)
            #pragma unroll
            for (int i = 0; i < 4; i++) acc[mt][nt][i] = 0.f;

    for (int k0 = 0; k0 < D_; k0 += 32) {
        // A tile 128x32 -> smem (tf32), coalesced float4 loads
        #pragma unroll
        for (int r = 0; r < 4; r++) {
            int slot = tid + r * 256;
            int row = slot >> 3, k4 = slot & 7;
            float4 v = *(const float4*)&A[(size_t)(m0 + row) * D_ + k0 + k4 * 4];
            uint4 u = make_uint4(f2t(v.x), f2t(v.y), f2t(v.z), f2t(v.w));
            *(uint4*)&As[row * 36 + k4 * 4] = u;
        }
        // B tile 32x64 -> smem
        #pragma unroll
        for (int r = 0; r < 2; r++) {
            int slot = tid + r * 256;
            int kr = slot >> 4, n4 = slot & 15;
            const float* src = (MODE == 0)
                ? &W[((size_t)(n0 >> 6) * D_ + (k0 + kr)) * E_ + n4 * 4]
                : &W[(size_t)(k0 + kr) * 1024 + n0 + n4 * 4];
            float4 v = *(const float4*)src;
            uint4 u = make_uint4(f2t(v.x), f2t(v.y), f2t(v.z), f2t(v.w));
            *(uint4*)&Bs[kr * 72 + n4 * 4] = u;
        }
        __syncthreads();

        #pragma unroll
        for (int ks = 0; ks < 4; ks++) {
            int kk = ks * 8;
            uint32_t af[2][4];
            #pragma unroll
            for (int mt = 0; mt < 2; mt++) {
                int row = wm * 32 + mt * 16 + g;
                af[mt][0] = As[row * 36 + kk + t];
                af[mt][1] = As[(row + 8) * 36 + kk + t];
                af[mt][2] = As[row * 36 + kk + 4 + t];
                af[mt][3] = As[(row + 8) * 36 + kk + 4 + t];
            }
            #pragma unroll
            for (int nt = 0; nt < 4; nt++) {
                int n = wn * 32 + nt * 8 + g;
                uint32_t bf[2];
                bf[0] = Bs[(kk + t) * 72 + n];
                bf[1] = Bs[(kk + 4 + t) * 72 + n];
                mma8(acc[0][nt], af[0], bf);
                mma8(acc[1][nt], af[1], bf);
            }
        }
        __syncthreads();
    }

    // epilogue
    #pragma unroll
    for (int nt = 0; nt < 4; nt++) {
        int nl = wn * 32 + nt * 8 + 2 * t;
        float b0 = bias[n0 + nl];
        float b1 = bias[n0 + nl + 1];
        #pragma unroll
        for (int mt = 0; mt < 2; mt++) {
            #pragma unroll
            for (int half = 0; half < 2; half++) {
                int m = m0 + wm * 32 + mt * 16 + g + half * 8;
                float2 r;
                r.x = acc[mt][nt][half * 2 + 0] + b0;
                r.y = acc[mt][nt][half * 2 + 1] + b1;
                if (MODE == 0) {
                    int b = m >> 11, s = m & 2047, h = n0 >> 6;
                    *(float2*)&C[(((size_t)(b * H_ + h) * S_ + s) * E_) + nl] = r;
                } else {
                    *(float2*)&C[(size_t)m * 1024 + n0 + nl] = r;
                }
            }
        }
    }
}

// ---------------------------------------------------------------------------
// Flash attention, tf32 tensor cores.
// Block: 128 q-rows of one (b,h); 8 warps, warp owns 16 q-rows.
// j streamed in 64-tiles. S=QK^T and O+=PV both via m16n8k8.
// smem (tf32 words, stride 68): Qs[128], Ks[64], Vt[64] (e-major), Ps[128]
// ---------------------------------------------------------------------------
#define ATT_SMEM_BYTES (68 * (128 + 64 + 64 + 128) * 4)

__global__ __launch_bounds__(256)
void attn_tc(const float* __restrict__ Qg_, const float* __restrict__ Kg_,
             const float* __restrict__ Vg_, float* __restrict__ Cc)
{
    extern __shared__ uint32_t sm[];
    uint32_t* Qs = sm;                  // [q128][e] stride 68
    uint32_t* Ks = Qs + 128 * 68;       // [j64][e]  stride 68
    uint32_t* Vt = Ks + 64 * 68;        // [e64][j]  stride 68
    uint32_t* Ps = Vt + 64 * 68;        // [q128][j] stride 68

    const int tid  = threadIdx.x;
    const int lane = tid & 31;
    const int wid  = tid >> 5;
    const int g    = lane >> 2;
    const int t    = lane & 3;
    const int bh   = blockIdx.y;
    const int q0   = blockIdx.x * 128;

    const float* Qg = Qg_ + (size_t)bh * S_ * E_;
    const float* Kg = Kg_ + (size_t)bh * S_ * E_;
    const float* Vg = Vg_ + (size_t)bh * S_ * E_;

    // Load Q tile (128x64) once
    #pragma unroll
    for (int r = 0; r < 8; r++) {
        int slot = tid + r * 256;
        int row = slot >> 4, e4 = slot & 15;
        float4 v = *(const float4*)&Qg[(size_t)(q0 + row) * E_ + e4 * 4];
        *(uint4*)&Qs[row * 68 + e4 * 4] =
            make_uint4(f2t(v.x), f2t(v.y), f2t(v.z), f2t(v.w));
    }

    const int wrow = wid * 16 + g;      // local q row (lo half of frag)

    float o[8][4];
    #pragma unroll
    for (int nt = 0; nt < 8; nt++)
        #pragma unroll
        for (int i = 0; i < 4; i++) o[nt][i] = 0.f;
    float mrow[2] = {-1e30f, -1e30f};
    float lrow[2] = {0.f, 0.f};

    for (int tt = 0; tt < S_ / 64; tt++) {
        __syncthreads();    // prior-tile consumers done; Q visible at tt=0
        // K tile 64x64 row-major
        #pragma unroll
        for (int r = 0; r < 4; r++) {
            int slot = tid + r * 256;
            int row = slot >> 4, e4 = slot & 15;
            float4 v = *(const float4*)&Kg[(size_t)(tt * 64 + row) * E_ + e4 * 4];
            *(uint4*)&Ks[row * 68 + e4 * 4] =
                make_uint4(f2t(v.x), f2t(v.y), f2t(v.z), f2t(v.w));
        }
        // V tile 64x64 transposed -> Vt[e][j] (lane map keeps STS 2-way max)
        {
            int j  = tid >> 2;
            int tl = tid & 3;
            #pragma unroll
            for (int r = 0; r < 4; r++) {
                int e4 = tl + 4 * r;
                float4 v = *(const float4*)&Vg[(size_t)(tt * 64 + j) * E_ + e4 * 4];
                Vt[(e4 * 4 + 0) * 68 + j] = f2t(v.x);
                Vt[(e4 * 4 + 1) * 68 + j] = f2t(v.y);
                Vt[(e4 * 4 + 2) * 68 + j] = f2t(v.z);
                Vt[(e4 * 4 + 3) * 68 + j] = f2t(v.w);
            }
        }
        __syncthreads();

        // S = Q K^T  (warp: 16q x 64j)
        float s[8][4];
        #pragma unroll
        for (int nt = 0; nt < 8; nt++)
            #pragma unroll
            for (int i = 0; i < 4; i++) s[nt][i] = 0.f;

        #pragma unroll
        for (int ks = 0; ks < 8; ks++) {
            int kk = ks * 8;
            uint32_t af[4];
            af[0] = Qs[wrow * 68 + kk + t];
            af[1] = Qs[(wrow + 8) * 68 + kk + t];
            af[2] = Qs[wrow * 68 + kk + 4 + t];
            af[3] = Qs[(wrow + 8) * 68 + kk + 4 + t];
            #pragma unroll
            for (int nt = 0; nt < 8; nt++) {
                int j = nt * 8 + g;
                uint32_t bf[2];
                bf[0] = Ks[j * 68 + kk + t];
                bf[1] = Ks[j * 68 + kk + 4 + t];
                mma8(s[nt], af, bf);
            }
        }

        // online softmax (rows wrow, wrow+8; 4-lane groups share a row)
        const float sc = 0.125f;
        float rmax[2] = {-1e30f, -1e30f};
        #pragma unroll
        for (int nt = 0; nt < 8; nt++) {
            #pragma unroll
            for (int i = 0; i < 4; i++) s[nt][i] *= sc;
            rmax[0] = fmaxf(rmax[0], fmaxf(s[nt][0], s[nt][1]));
            rmax[1] = fmaxf(rmax[1], fmaxf(s[nt][2], s[nt][3]));
        }
        #pragma unroll
        for (int h = 0; h < 2; h++) {
            rmax[h] = fmaxf(rmax[h], __shfl_xor_sync(0xffffffffu, rmax[h], 1));
            rmax[h] = fmaxf(rmax[h], __shfl_xor_sync(0xffffffffu, rmax[h], 2));
        }
        float mnew[2], corr[2], rsum[2] = {0.f, 0.f};
        #pragma unroll
        for (int h = 0; h < 2; h++) {
            mnew[h] = fmaxf(mrow[h], rmax[h]);
            corr[h] = __expf(mrow[h] - mnew[h]);
        }
        #pragma unroll
        for (int nt = 0; nt < 8; nt++) {
            float p0 = __expf(s[nt][0] - mnew[0]);
            float p1 = __expf(s[nt][1] - mnew[0]);
            float p2 = __expf(s[nt][2] - mnew[1]);
            float p3 = __expf(s[nt][3] - mnew[1]);
            s[nt][0] = p0; s[nt][1] = p1; s[nt][2] = p2; s[nt][3] = p3;
            rsum[0] += p0 + p1;
            rsum[1] += p2 + p3;
        }
        #pragma unroll
        for (int h = 0; h < 2; h++) {
            rsum[h] += __shfl_xor_sync(0xffffffffu, rsum[h], 1);
            rsum[h] += __shfl_xor_sync(0xffffffffu, rsum[h], 2);
            lrow[h] = lrow[h] * corr[h] + rsum[h];
            mrow[h] = mnew[h];
        }
        #pragma unroll
        for (int nt = 0; nt < 8; nt++) {
            o[nt][0] *= corr[0]; o[nt][1] *= corr[0];
            o[nt][2] *= corr[1]; o[nt][3] *= corr[1];
        }
        // write P (tf32) to smem for the PV mma
        #pragma unroll
        for (int nt = 0; nt < 8; nt++) {
            int col = nt * 8 + 2 * t;
            *(uint2*)&Ps[wrow * 68 + col] =
                make_uint2(f2t(s[nt][0]), f2t(s[nt][1]));
            *(uint2*)&Ps[(wrow + 8) * 68 + col] =
                make_uint2(f2t(s[nt][2]), f2t(s[nt][3]));
        }
        __syncwarp();

        // O += P V  (warp-local P rows)
        #pragma unroll
        for (int ks = 0; ks < 8; ks++) {
            int kk = ks * 8;
            uint32_t af[4];
            af[0] = Ps[wrow * 68 + kk + t];
            af[1] = Ps[(wrow + 8) * 68 + kk + t];
            af[2] = Ps[wrow * 68 + kk + 4 + t];
            af[3] = Ps[(wrow + 8) * 68 + kk + 4 + t];
            #pragma unroll
            for (int nt = 0; nt < 8; nt++) {
                int e = nt * 8 + g;
                uint32_t bf[2];
                bf[0] = Vt[e * 68 + kk + t];
                bf[1] = Vt[e * 68 + kk + 4 + t];
                mma8(o[nt], af, bf);
            }
        }
    }

    // epilogue: normalize, store to concat layout [b][s][h*64+e]
    const int b = bh >> 4;
    const int h = bh & 15;
    float inv0 = 1.f / lrow[0];
    float inv1 = 1.f / lrow[1];
    #pragma unroll
    for (int nt = 0; nt < 8; nt++) {
        int e = nt * 8 + 2 * t;
        int qlo = q0 + wrow;
        float2 r0 = make_float2(o[nt][0] * inv0, o[nt][1] * inv0);
        float2 r1 = make_float2(o[nt][2] * inv1, o[nt][3] * inv1);
        *(float2*)&Cc[((size_t)(b * S_ + qlo) * H_ + h) * E_ + e] = r0;
        *(float2*)&Cc[((size_t)(b * S_ + qlo + 8) * H_ + h) * E_ + e] = r1;
    }
}

// ---------------------------------------------------------------------------
extern "C" void kernel_launch(void* const* d_in, const int* in_sizes, int n_in,
                              void* d_out, int out_size)
{
    const float* q  = (const float*)d_in[0];
    const float* k  = (const float*)d_in[1];
    const float* v  = (const float*)d_in[2];
    const float* Wq = (const float*)d_in[3];
    const float* bq = (const float*)d_in[4];
    const float* Wk = (const float*)d_in[5];
    const float* bk = (const float*)d_in[6];
    const float* Wv = (const float*)d_in[7];
    const float* bv = (const float*)d_in[8];
    const float* Wo = (const float*)d_in[9];
    const float* bo = (const float*)d_in[10];
    float* out = (float*)d_out;

    float *gq, *gk, *gv, *gc;
    cudaGetSymbolAddress((void**)&gq, g_Q);
    cudaGetSymbolAddress((void**)&gk, g_K);
    cudaGetSymbolAddress((void**)&gv, g_V);
    cudaGetSymbolAddress((void**)&gc, g_Cc);

    dim3 pg(16, 64);   // N/64, M/128

    gemm_tc<0><<<pg, 256>>>(q, Wq, bq, gq);
    gemm_tc<0><<<pg, 256>>>(k, Wk, bk, gk);
    gemm_tc<0><<<pg, 256>>>(v, Wv, bv, gv);

    cudaFuncSetAttribute(attn_tc,
                         cudaFuncAttributeMaxDynamicSharedMemorySize,
                         ATT_SMEM_BYTES);
    attn_tc<<<dim3(S_ / 128, B_ * H_), 256, ATT_SMEM_BYTES>>>(gq, gk, gv, gc);

    gemm_tc<1><<<pg, 256>>>(gc, Wo, bo, out);
}